// round 8
// baseline (speedup 1.0000x reference)
#include <cuda_runtime.h>
#include <cstdint>

// BinCat: idx = sum_j (1 - x[b,i,j]) * 2^(19-j), out[row,:] = cats[idx,:]
// x:    (4096, 16, 20) int32 (0/1)   -> 65536 rows of 80 B (16B-aligned)
// cats: (2^20, 64) float32           -> 256 B rows
// out:  (4096, 16, 64) float32
//
// R6: two-kernel split.
//   Kernel A: compute all row indices into __device__ scratch (streaming,
//             ~0.6us). Removes the 600-cycle x-load chain from the gather.
//   Kernel B: pure gather. Warp handles 8 rows as 4 float4 pairs — each
//             LDG.128 covers 2 rows (lanes 0-15 row 2p, lanes 16-31 row
//             2p+1). Index reads are broadcast hits on the 256KB scratch.
//             12 mem instructions / 8 rows (vs 21 in R4), fully
//             front-batchable -> L1tex queue stays full of gather lines.

static constexpr int LENGTH   = 20;
static constexpr int DIM      = 64;
static constexpr int MAX_ROWS = 4096 * 16;      // 65536

__device__ unsigned g_idx[MAX_ROWS];

// ---------------- Kernel A: index computation ----------------
__global__ void __launch_bounds__(256)
bincat_index_kernel(const int* __restrict__ x, int nrows)
{
    const int row = blockIdx.x * blockDim.x + threadIdx.x;
    if (row >= nrows) return;

    const int4* __restrict__ xr =
        reinterpret_cast<const int4*>(x + (size_t)row * LENGTH);
    const int4 a0 = __ldg(&xr[0]);
    const int4 a1 = __ldg(&xr[1]);
    const int4 a2 = __ldg(&xr[2]);
    const int4 a3 = __ldg(&xr[3]);
    const int4 a4 = __ldg(&xr[4]);
    const int v[LENGTH] = { a0.x, a0.y, a0.z, a0.w,
                            a1.x, a1.y, a1.z, a1.w,
                            a2.x, a2.y, a2.z, a2.w,
                            a3.x, a3.y, a3.z, a3.w,
                            a4.x, a4.y, a4.z, a4.w };
    unsigned idx = 0u;
    #pragma unroll
    for (int j = 0; j < LENGTH; ++j)
        idx |= (unsigned)(1 - v[j]) << (LENGTH - 1 - j);

    g_idx[row] = idx;
}

// ---------------- Kernel B: gather ----------------
static constexpr int ROWS_PER_WARP = 8;      // 4 float4-pairs
static constexpr int PAIRS         = ROWS_PER_WARP / 2;
static constexpr int F4_PER_ROW    = DIM / 4;  // 16

__global__ void __launch_bounds__(256)
bincat_gather_kernel(const float* __restrict__ cats,
                     float* __restrict__ out,
                     int nrows)
{
    const int gtid    = blockIdx.x * blockDim.x + threadIdx.x;
    const int warp_id = gtid >> 5;
    const int lane    = threadIdx.x & 31;
    const int row0    = warp_id * ROWS_PER_WARP;
    if (row0 >= nrows) return;

    const int half = lane >> 4;        // 0: even row of pair, 1: odd row
    const int col  = lane & 15;        // float4 column within row

    const float4* __restrict__ cats4 = reinterpret_cast<const float4*>(cats);
    float4*       __restrict__ out4  = reinterpret_cast<float4*>(out);

    // --- fetch the 8 indices (broadcast loads on 256KB scratch: L1/L2 hits) ---
    unsigned ridx[PAIRS];
    int      rrow[PAIRS];
    #pragma unroll
    for (int p = 0; p < PAIRS; ++p) {
        const int r = row0 + 2 * p + half;      // this lane's row for pair p
        rrow[p] = r;
        ridx[p] = (r < nrows) ? g_idx[r] : 0u;
    }

    // --- issue ALL gather loads (4 independent LDG.128, 16 lines in flight) ---
    float4 v[PAIRS];
    #pragma unroll
    for (int p = 0; p < PAIRS; ++p)
        v[p] = __ldg(&cats4[(size_t)ridx[p] * F4_PER_ROW + col]);

    // --- store all rows (coalesced STG.128) ---
    #pragma unroll
    for (int p = 0; p < PAIRS; ++p) {
        if (rrow[p] < nrows)
            out4[(size_t)rrow[p] * F4_PER_ROW + col] = v[p];
    }
}

extern "C" void kernel_launch(void* const* d_in, const int* in_sizes, int n_in,
                              void* d_out, int out_size)
{
    const int*   x    = (const int*)d_in[0];    // (B, I, 20) int32
    const float* cats = (const float*)d_in[1];  // (2^20, 64) float32
    float*       out  = (float*)d_out;          // (B, I, 64) float32

    int nrows = in_sizes[0] / LENGTH;           // 65536
    if (nrows > MAX_ROWS) nrows = MAX_ROWS;

    // Kernel A: one thread per row
    {
        const int threads = 256;
        const int blocks  = (nrows + threads - 1) / threads;   // 256
        bincat_index_kernel<<<blocks, threads>>>(x, nrows);
    }

    // Kernel B: one warp per 8 rows, 8 warps per block
    {
        const int threads        = 256;
        const int rows_per_block = (threads / 32) * ROWS_PER_WARP;  // 64
        const int blocks = (nrows + rows_per_block - 1) / rows_per_block; // 1024
        bincat_gather_kernel<<<blocks, threads>>>(cats, out, nrows);
    }
}

// round 9
// speedup vs baseline: 1.2007x; 1.2007x over previous
#include <cuda_runtime.h>
#include <cstdint>

// BinCat: idx = sum_j (1 - x[b,i,j]) * 2^(19-j), out[row,:] = cats[idx,:]
// x:    (4096, 16, 20) int32 (0/1)   -> 65536 rows of 80 B (16B-aligned)
// cats: (2^20, 64) float32           -> 256 B rows (2 full 128B lines)
// out:  (4096, 16, 64) float32
//
// R9 = R4 (best: 8.7us) + L2-residency management + finer grid.
//   * The harness times graph REPLAYS: same 268MB cats table every run, L2
//     is 126MB -> keep cats lines resident across replays by streaming the
//     write-once output (__stcs, evict-first) and the x reads (__ldcs)
//     around L2 instead of letting them thrash it.
//   * 128-thread blocks (2048 CTAs) for better wave balance / more
//     resident warps than R4's 256-thread blocks.
//   Gather structure unchanged from R4: one warp = 8 rows, load-all (8
//   independent 256B reads, 16 lines in flight) then store-all.

static constexpr int LENGTH        = 20;
static constexpr int DIM           = 64;
static constexpr int ROWS_PER_WARP = 8;

__global__ void __launch_bounds__(128)
bincat_gather_kernel(const int* __restrict__ x,
                     const float* __restrict__ cats,
                     float* __restrict__ out,
                     int nrows)
{
    const int gtid     = blockIdx.x * blockDim.x + threadIdx.x;
    const int warp_id  = gtid >> 5;
    const int lane     = threadIdx.x & 31;
    const int row_base = warp_id * ROWS_PER_WARP;
    if (row_base >= nrows) return;

    // ---- Phase 1: lanes 0..7 compute indices (rows are 80 B = 5 x int4) ----
    // x is streamed once per replay -> evict-first loads, don't pollute L2.
    unsigned idx = 0u;
    if (lane < ROWS_PER_WARP) {
        const int myrow = row_base + lane;
        if (myrow < nrows) {
            const int4* __restrict__ xr =
                reinterpret_cast<const int4*>(x + (size_t)myrow * LENGTH);
            const int4 a0 = __ldcs(&xr[0]);
            const int4 a1 = __ldcs(&xr[1]);
            const int4 a2 = __ldcs(&xr[2]);
            const int4 a3 = __ldcs(&xr[3]);
            const int4 a4 = __ldcs(&xr[4]);
            const int v[LENGTH] = { a0.x, a0.y, a0.z, a0.w,
                                    a1.x, a1.y, a1.z, a1.w,
                                    a2.x, a2.y, a2.z, a2.w,
                                    a3.x, a3.y, a3.z, a3.w,
                                    a4.x, a4.y, a4.z, a4.w };
            #pragma unroll
            for (int j = 0; j < LENGTH; ++j)
                idx |= (unsigned)(1 - v[j]) << (LENGTH - 1 - j);
        }
    }

    // ---- Phase 2a: broadcast indices, issue ALL gather loads ----
    unsigned ridx[ROWS_PER_WARP];
    #pragma unroll
    for (int i = 0; i < ROWS_PER_WARP; ++i)
        ridx[i] = __shfl_sync(0xffffffffu, idx, i);

    // cats gathers use default caching (__ldg) so rows persist in L2
    // across graph replays (126MB L2 vs 268MB table ~ 47% resident).
    float2 v[ROWS_PER_WARP];
    #pragma unroll
    for (int i = 0; i < ROWS_PER_WARP; ++i) {
        const float2* __restrict__ src =
            reinterpret_cast<const float2*>(cats + (size_t)ridx[i] * DIM);
        v[i] = __ldg(&src[lane]);           // 8 independent 256B reads
    }

    // ---- Phase 2b: store all rows, evict-first (write-once stream) ----
    #pragma unroll
    for (int i = 0; i < ROWS_PER_WARP; ++i) {
        const int r = row_base + i;
        if (r < nrows) {
            float2* __restrict__ dst =
                reinterpret_cast<float2*>(out + (size_t)r * DIM);
            __stcs(&dst[lane], v[i]);
        }
    }
}

extern "C" void kernel_launch(void* const* d_in, const int* in_sizes, int n_in,
                              void* d_out, int out_size)
{
    const int*   x    = (const int*)d_in[0];    // (B, I, 20) int32
    const float* cats = (const float*)d_in[1];  // (2^20, 64) float32
    float*       out  = (float*)d_out;          // (B, I, 64) float32

    const int nrows = in_sizes[0] / LENGTH;     // 65536

    const int threads = 128;                                   // 4 warps
    const int rows_per_block = (threads / 32) * ROWS_PER_WARP; // 32 rows
    const int blocks = (nrows + rows_per_block - 1) / rows_per_block; // 2048

    bincat_gather_kernel<<<blocks, threads>>>(x, cats, out, nrows);
}